// round 1
// baseline (speedup 1.0000x reference)
#include <cuda_runtime.h>
#include <math.h>

// ---------------------------------------------------------------------------
// Problem constants
//   B_T=32, N=2048, E=8192, D=128, T=8, B=4, dh=16, H=8 (head == timestep)
//   Q rows    : 65536  (= 32*2048)
//   Edge rows : 262144 (= 32*8192)
//   Only the edge_attr branch matters (x_0 branch result is overwritten).
// ---------------------------------------------------------------------------

#define KKV_BLOCKS 2048   // 262144 / 128
#define KQ_BLOCKS  512    // 65536  / 128
#define KO_BLOCKS  512

// Scratch (static device globals; no allocation)
__device__ float g_q[65536 * 128];        // processed q (softmax+rope), q_data row layout
__device__ float g_part[KKV_BLOCKS * 272]; // per-tile kv[16][16] + ksum[16] partials
__device__ float g_kv[32 * 256];          // kv per b_t
__device__ float g_ksum[32 * 16];         // ksum per b_t

// freqs[j] = 10000^(-j/8) = 10^(-j/2)
__constant__ float c_freq[8] = {
    1.0f, 0.31622776601683794f, 0.1f, 0.031622776601683794f,
    0.01f, 0.0031622776601683794f, 0.001f, 0.00031622776601683794f};

// ---------------------------------------------------------------------------
// Shared tile helpers: tiles are 128x128 fp32 (64KB)
// ---------------------------------------------------------------------------
__device__ __forceinline__ void load_A_tile(float* As, const float* Ag, int tid) {
    const float4* a4 = reinterpret_cast<const float4*>(Ag);
    float4* s4 = reinterpret_cast<float4*>(As);
#pragma unroll
    for (int k = 0; k < 16; k++) s4[tid + 256 * k] = a4[tid + 256 * k];
}

// Ws[k][j] = W[j][k]  (so inner loop reads Ws[kk*128 + col] contiguously)
__device__ __forceinline__ void load_W_T(float* Ws, const float* Wg, int tid) {
    const float4* w4 = reinterpret_cast<const float4*>(Wg);
#pragma unroll
    for (int k = 0; k < 16; k++) {
        int idx = tid + 256 * k;
        int j = idx >> 5, k4 = idx & 31;
        float4 w = w4[idx];
        Ws[(k4 * 4 + 0) * 128 + j] = w.x;
        Ws[(k4 * 4 + 1) * 128 + j] = w.y;
        Ws[(k4 * 4 + 2) * 128 + j] = w.z;
        Ws[(k4 * 4 + 3) * 128 + j] = w.w;
    }
}

// C[128][128] = A[128][128] @ W^T ; thread (ty,tx) owns rows ty*8..+7, cols tx*8..+7
__device__ __forceinline__ void gemm128(const float* __restrict__ As,
                                        const float* __restrict__ Ws,
                                        int ty, int tx, float acc[8][8]) {
    const float* arow = As + ty * 8 * 128;
    const float* wcol = Ws + tx * 8;
#pragma unroll 4
    for (int kk = 0; kk < 128; kk++) {
        float a[8];
#pragma unroll
        for (int i = 0; i < 8; i++) a[i] = arow[i * 128 + kk];
        float4 w0 = *reinterpret_cast<const float4*>(wcol + kk * 128);
        float4 w1 = *reinterpret_cast<const float4*>(wcol + kk * 128 + 4);
#pragma unroll
        for (int i = 0; i < 8; i++) {
            acc[i][0] = fmaf(a[i], w0.x, acc[i][0]);
            acc[i][1] = fmaf(a[i], w0.y, acc[i][1]);
            acc[i][2] = fmaf(a[i], w0.z, acc[i][2]);
            acc[i][3] = fmaf(a[i], w0.w, acc[i][3]);
            acc[i][4] = fmaf(a[i], w1.x, acc[i][4]);
            acc[i][5] = fmaf(a[i], w1.y, acc[i][5]);
            acc[i][6] = fmaf(a[i], w1.z, acc[i][6]);
            acc[i][7] = fmaf(a[i], w1.w, acc[i][7]);
        }
    }
}

__device__ __forceinline__ void zero_acc(float acc[8][8]) {
#pragma unroll
    for (int i = 0; i < 8; i++)
#pragma unroll
        for (int j = 0; j < 8; j++) acc[i][j] = 0.0f;
}

__device__ __forceinline__ void load16(float* x, const float* p) {
#pragma unroll
    for (int q4 = 0; q4 < 4; q4++) {
        float4 v = *reinterpret_cast<const float4*>(p + q4 * 4);
        x[q4 * 4 + 0] = v.x; x[q4 * 4 + 1] = v.y;
        x[q4 * 4 + 2] = v.z; x[q4 * 4 + 3] = v.w;
    }
}
__device__ __forceinline__ void store16(float* p, const float* x) {
#pragma unroll
    for (int q4 = 0; q4 < 4; q4++) {
        float4 v = make_float4(x[q4 * 4 + 0], x[q4 * 4 + 1],
                               x[q4 * 4 + 2], x[q4 * 4 + 3]);
        *reinterpret_cast<float4*>(p + q4 * 4) = v;
    }
}

__device__ __forceinline__ void softmax16(float* x) {
    float mx = x[0];
#pragma unroll
    for (int e = 1; e < 16; e++) mx = fmaxf(mx, x[e]);
    float s = 0.0f;
#pragma unroll
    for (int e = 0; e < 16; e++) { x[e] = __expf(x[e] - mx); s += x[e]; }
    float inv = 1.0f / s;
#pragma unroll
    for (int e = 0; e < 16; e++) x[e] *= inv;
}

__device__ __forceinline__ void rope16(float* x, int pos) {
    float fp = (float)pos;
#pragma unroll
    for (int j = 0; j < 8; j++) {
        float sn, cs;
        __sincosf(fp * c_freq[j], &sn, &cs);
        float a = x[2 * j], b = x[2 * j + 1];
        x[2 * j]     = a * cs - b * sn;
        x[2 * j + 1] = a * sn + b * cs;
    }
}

// ---------------------------------------------------------------------------
// Kernel 1: Q path.  qf = q_data @ Wq^T + bq; softmax(16-groups); rope(pos=n/256)
// ---------------------------------------------------------------------------
__global__ void __launch_bounds__(256, 1)
kq_kernel(const float* __restrict__ Q, const float* __restrict__ Wq,
          const float* __restrict__ bq) {
    extern __shared__ float sm[];
    float* As = sm;           // 16384 floats (reused as C stage)
    float* Ws = sm + 16384;   // 16384 floats
    int tid = threadIdx.x;
    int ty = tid >> 4, tx = tid & 15;
    int row0 = blockIdx.x * 128;

    load_A_tile(As, Q + (size_t)row0 * 128, tid);
    load_W_T(Ws, Wq, tid);
    __syncthreads();

    float acc[8][8];
    zero_acc(acc);
    gemm128(As, Ws, ty, tx, acc);
    __syncthreads();  // all reads of As done before overwrite

    float bj[8];
#pragma unroll
    for (int j = 0; j < 8; j++) bj[j] = bq[tx * 8 + j];
#pragma unroll
    for (int i = 0; i < 8; i++)
#pragma unroll
        for (int j = 0; j < 8; j++)
            As[(ty * 8 + i) * 128 + tx * 8 + j] = acc[i][j] + bj[j];
    __syncthreads();

    // epilogue: 128 rows x 8 groups = 1024 tasks, 4 per thread
#pragma unroll
    for (int it = 0; it < 4; it++) {
        int task = it * 256 + tid;
        int r = task >> 3, g = task & 7;
        int rg = row0 + r;
        int n = rg & 2047;
        int pos = n >> 8;  // n/256
        float x[16];
        load16(x, As + r * 128 + g * 16);
        softmax16(x);      // softmax BEFORE rope for q
        rope16(x, pos);
        store16(g_q + (size_t)rg * 128 + g * 16, x);
    }
}

// ---------------------------------------------------------------------------
// Kernel 2: edge K/V path, fully fused.
//   k = edge @ Wk^T + bk; rope(pos=m/1024); softmax
//   v = edge @ Wv^T + bv
//   partial kv[16][16] += sum_{row,g} k16 (x) v16 ; partial ksum[16] += k16
// ---------------------------------------------------------------------------
__global__ void __launch_bounds__(256, 1)
kkv_kernel(const float* __restrict__ E,
           const float* __restrict__ Wk, const float* __restrict__ bk,
           const float* __restrict__ Wv, const float* __restrict__ bv) {
    extern __shared__ float sm[];
    float* As = sm;            // edge tile, later V tile
    float* Ws = sm + 16384;    // Wk^T, then Wv^T, then reduction buffer
    float* Ks = sm + 32768;    // processed k tile
    int tid = threadIdx.x;
    int ty = tid >> 4, tx = tid & 15;
    int blk = blockIdx.x;
    int row0 = blk * 128;

    load_A_tile(As, E + (size_t)row0 * 128, tid);
    load_W_T(Ws, Wk, tid);
    __syncthreads();

    float acc[8][8];
    zero_acc(acc);
    gemm128(As, Ws, ty, tx, acc);  // k = edge @ Wk^T

    {
        float bj[8];
#pragma unroll
        for (int j = 0; j < 8; j++) bj[j] = bk[tx * 8 + j];
#pragma unroll
        for (int i = 0; i < 8; i++)
#pragma unroll
            for (int j = 0; j < 8; j++)
                Ks[(ty * 8 + i) * 128 + tx * 8 + j] = acc[i][j] + bj[j];
    }
    __syncthreads();  // Ks complete; also ensures all Ws(k) reads finished

    // k epilogue: rope then softmax, in place in Ks
#pragma unroll
    for (int it = 0; it < 4; it++) {
        int task = it * 256 + tid;
        int r = task >> 3, g = task & 7;
        int m = (row0 + r) & 8191;
        int pos = m >> 10;  // m/1024
        float x[16];
        load16(x, Ks + r * 128 + g * 16);
        rope16(x, pos);     // rope BEFORE softmax for k
        softmax16(x);
        store16(Ks + r * 128 + g * 16, x);
    }
    load_W_T(Ws, Wv, tid);  // overwrite Wk^T with Wv^T (no reads of Ws in flight)
    __syncthreads();

    zero_acc(acc);
    gemm128(As, Ws, ty, tx, acc);  // v = edge @ Wv^T
    __syncthreads();  // all reads of As done before overwrite with V

    {
        float bj[8];
#pragma unroll
        for (int j = 0; j < 8; j++) bj[j] = bv[tx * 8 + j];
#pragma unroll
        for (int i = 0; i < 8; i++)
#pragma unroll
            for (int j = 0; j < 8; j++)
                As[(ty * 8 + i) * 128 + tx * 8 + j] = acc[i][j] + bj[j];
    }
    __syncthreads();

    // kv reduction: 1024 (row,g) items split across 8 warps; lane owns
    // (d1 = lane/2, d2 half = (lane&1)*8).
    int warp = tid >> 5, lane = tid & 31;
    int d1 = lane >> 1;
    int d2b = (lane & 1) * 8;
    float kvacc[8] = {0, 0, 0, 0, 0, 0, 0, 0};
    float ksacc = 0.0f;
    for (int item = warp * 128; item < warp * 128 + 128; item++) {
        int r = item >> 3, g = item & 7;
        float kval = Ks[r * 128 + g * 16 + d1];
        const float4* vp = reinterpret_cast<const float4*>(As + r * 128 + g * 16 + d2b);
        float4 v0 = vp[0], v1 = vp[1];
        kvacc[0] = fmaf(kval, v0.x, kvacc[0]);
        kvacc[1] = fmaf(kval, v0.y, kvacc[1]);
        kvacc[2] = fmaf(kval, v0.z, kvacc[2]);
        kvacc[3] = fmaf(kval, v0.w, kvacc[3]);
        kvacc[4] = fmaf(kval, v1.x, kvacc[4]);
        kvacc[5] = fmaf(kval, v1.y, kvacc[5]);
        kvacc[6] = fmaf(kval, v1.z, kvacc[6]);
        kvacc[7] = fmaf(kval, v1.w, kvacc[7]);
        ksacc += kval;
    }
    // cross-warp reduce via smem (reuse Ws region): red[warp][d1][17]
    float* red = Ws;
#pragma unroll
    for (int jj = 0; jj < 8; jj++)
        red[warp * 272 + d1 * 17 + d2b + jj] = kvacc[jj];
    if ((lane & 1) == 0) red[warp * 272 + d1 * 17 + 16] = ksacc;
    __syncthreads();

    for (int e = tid; e < 272; e += 256) {
        float s = 0.0f;
#pragma unroll
        for (int w = 0; w < 8; w++) s += red[w * 272 + e];
        g_part[(size_t)blk * 272 + e] = s;
    }
}

// ---------------------------------------------------------------------------
// Kernel 3: deterministic fixed-order reduction of per-tile partials
// ---------------------------------------------------------------------------
__global__ void kr_kernel() {
    int bt = blockIdx.x;   // 0..31
    int tid = threadIdx.x; // 272 threads
    float s = 0.0f;
    for (int i = 0; i < 64; i++)
        s += g_part[(size_t)(bt * 64 + i) * 272 + tid];
    int d1 = tid / 17, col = tid % 17;
    if (col < 16) g_kv[bt * 256 + d1 * 16 + col] = s;
    else          g_ksum[bt * 16 + d1] = s;
}

// ---------------------------------------------------------------------------
// Kernel 4: output.  Build Y rows (q + (q@kv)*Dinv across all 8 heads),
// then Y @ Wo^T + bo. Output flat index is linear (transpose+reshape = id).
// ---------------------------------------------------------------------------
__global__ void __launch_bounds__(256, 1)
ko_kernel(const float* __restrict__ Wo, const float* __restrict__ bo,
          float* __restrict__ out) {
    extern __shared__ float sm[];
    float* Ys  = sm;            // 16384
    float* Ws  = sm + 16384;    // 16384
    float* kvs = sm + 32768;    // 2048 : [t][d][e]
    float* kss = sm + 34816;    // 128  : [t][d]
    int tid = threadIdx.x;
    int ty = tid >> 4, tx = tid & 15;
    int r0 = blockIdx.x * 128;
    int b = r0 >> 14;  // batch (0..3)

    for (int idx = tid; idx < 2048; idx += 256) kvs[idx] = g_kv[b * 2048 + idx];
    if (tid < 128) kss[tid] = g_ksum[b * 128 + tid];
    load_W_T(Ws, Wo, tid);
    __syncthreads();

    // build Y: 128 rows x 8 heads(t) = 1024 tasks
#pragma unroll
    for (int it = 0; it < 4; it++) {
        int task = it * 256 + tid;
        int r = task >> 3, t = task & 7;
        int spp = (r0 + r) & 16383;   // s' within batch
        int n = spp >> 3, g = spp & 7;
        const float* qp = g_q + (size_t)((b * 8 + t) * 2048 + n) * 128 + g * 16;
        float q16[16];
        load16(q16, qp);
        float den = 0.0f;
#pragma unroll
        for (int d = 0; d < 16; d++) den = fmaf(q16[d], kss[t * 16 + d], den);
        float dinv = 1.0f / fmaxf(den, 1e-8f);
        float a16[16];
#pragma unroll
        for (int e = 0; e < 16; e++) a16[e] = 0.0f;
#pragma unroll
        for (int d = 0; d < 16; d++) {
            float qd = q16[d];
            float kk16[16];
            load16(kk16, kvs + t * 256 + d * 16);
#pragma unroll
            for (int e = 0; e < 16; e++) a16[e] = fmaf(qd, kk16[e], a16[e]);
        }
        float o16[16];
#pragma unroll
        for (int e = 0; e < 16; e++) o16[e] = q16[e] + a16[e] * dinv;
        store16(Ys + r * 128 + t * 16, o16);
    }
    __syncthreads();

    float acc[8][8];
    zero_acc(acc);
    gemm128(Ys, Ws, ty, tx, acc);

    float bj[8];
#pragma unroll
    for (int j = 0; j < 8; j++) bj[j] = bo[tx * 8 + j];
#pragma unroll
    for (int i = 0; i < 8; i++) {
        size_t row = (size_t)(r0 + ty * 8 + i);
        float4 o0 = make_float4(acc[i][0] + bj[0], acc[i][1] + bj[1],
                                acc[i][2] + bj[2], acc[i][3] + bj[3]);
        float4 o1 = make_float4(acc[i][4] + bj[4], acc[i][5] + bj[5],
                                acc[i][6] + bj[6], acc[i][7] + bj[7]);
        *reinterpret_cast<float4*>(out + row * 128 + tx * 8)     = o0;
        *reinterpret_cast<float4*>(out + row * 128 + tx * 8 + 4) = o1;
    }
}

// ---------------------------------------------------------------------------
// Host launcher
// ---------------------------------------------------------------------------
extern "C" void kernel_launch(void* const* d_in, const int* in_sizes, int n_in,
                              void* d_out, int out_size) {
    const float* edge = (const float*)d_in[1];
    const float* qd   = (const float*)d_in[2];
    const float* Wq   = (const float*)d_in[3];
    const float* bq   = (const float*)d_in[4];
    const float* Wk1  = (const float*)d_in[9];
    const float* bk1  = (const float*)d_in[10];
    const float* Wv1  = (const float*)d_in[11];
    const float* bv1  = (const float*)d_in[12];
    const float* Wo   = (const float*)d_in[13];
    const float* bo   = (const float*)d_in[14];
    float* out = (float*)d_out;

    cudaFuncSetAttribute(kq_kernel,  cudaFuncAttributeMaxDynamicSharedMemorySize, 131072);
    cudaFuncSetAttribute(kkv_kernel, cudaFuncAttributeMaxDynamicSharedMemorySize, 196608);
    cudaFuncSetAttribute(ko_kernel,  cudaFuncAttributeMaxDynamicSharedMemorySize, 139776);

    kq_kernel<<<KQ_BLOCKS, 256, 131072>>>(qd, Wq, bq);
    kkv_kernel<<<KKV_BLOCKS, 256, 196608>>>(edge, Wk1, bk1, Wv1, bv1);
    kr_kernel<<<32, 272>>>();
    ko_kernel<<<KO_BLOCKS, 256, 139776>>>(Wo, bo, out);
}

// round 2
// speedup vs baseline: 2.6085x; 2.6085x over previous
#include <cuda_runtime.h>
#include <math.h>
#include <stdint.h>

// ---------------------------------------------------------------------------
// B_T=32, N=2048, E=8192, D=128, T=8, B=4, dh=16, H=8 (head == timestep)
// Only the edge_attr branch matters (x_0 branch result is overwritten).
// All big GEMMs via mma.sync.m16n8k8.tf32 (tensor pipe).
// ---------------------------------------------------------------------------

#define KKV_BLOCKS 2048
#define KQ_BLOCKS  512
#define KO_BLOCKS  512
#define LDP 136              // padded row stride (floats) for 128-wide tiles

__device__ float g_q[65536 * 128];          // processed q (fp32)
__device__ float g_part[KKV_BLOCKS * 272];  // per-tile kv[16][16]+ksum[16]
__device__ float g_kv[32 * 256];
__device__ float g_ksum[32 * 16];

__constant__ float c_freq[8] = {
    1.0f, 0.31622776601683794f, 0.1f, 0.031622776601683794f,
    0.01f, 0.0031622776601683794f, 0.001f, 0.00031622776601683794f};

// ---------------------------------------------------------------------------
// TF32 helpers
// ---------------------------------------------------------------------------
__device__ __forceinline__ float cvt_tf32(float x) {
    uint32_t u;
    asm("cvt.rna.tf32.f32 %0, %1;" : "=r"(u) : "f"(x));
    return __uint_as_float(u);
}
__device__ __forceinline__ uint32_t f2u(float x) { return __float_as_uint(x); }

__device__ __forceinline__ void mma8(float c[4], const uint32_t a[4],
                                     uint32_t b0, uint32_t b1) {
    asm volatile(
        "mma.sync.aligned.m16n8k8.row.col.f32.tf32.tf32.f32 "
        "{%0,%1,%2,%3}, {%4,%5,%6,%7}, {%8,%9}, {%0,%1,%2,%3};"
        : "+f"(c[0]), "+f"(c[1]), "+f"(c[2]), "+f"(c[3])
        : "r"(a[0]), "r"(a[1]), "r"(a[2]), "r"(a[3]), "r"(b0), "r"(b1));
}

// ---------------------------------------------------------------------------
// Tile load: 128x128 fp32 from gmem -> smem (stride LDP), tf32-rounded
// ---------------------------------------------------------------------------
__device__ __forceinline__ void load_tile_cvt(float* S, const float* G, int tid) {
    const float4* g4 = reinterpret_cast<const float4*>(G);
#pragma unroll
    for (int k = 0; k < 16; k++) {
        int idx = tid + 256 * k;
        int row = idx >> 5, c4 = idx & 31;
        float4 v = g4[idx];
        float4 o = make_float4(cvt_tf32(v.x), cvt_tf32(v.y),
                               cvt_tf32(v.z), cvt_tf32(v.w));
        *reinterpret_cast<float4*>(S + row * LDP + c4 * 4) = o;
    }
}

// ---------------------------------------------------------------------------
// 128x128x128 GEMM: C = A(row-major, LDP) @ W^T (W stored row-major, LDP).
// Warp w: mwarp=w>>1 (32 rows), nwarp=w&1 (64 cols). acc C[2][8][4].
// ---------------------------------------------------------------------------
__device__ __forceinline__ void mma_gemm128(const float* __restrict__ As,
                                            const float* __restrict__ Ws,
                                            float C[2][8][4], int warp, int lane) {
    int mw = warp >> 1, nw = warp & 1;
    int qrow = lane >> 2, qk = lane & 3;
    const float* Abase = As + (mw * 32 + qrow) * LDP + qk;
    const float* Bbase = Ws + (nw * 64 + qrow) * LDP + qk;
#pragma unroll
    for (int ks = 0; ks < 16; ks++) {
        int k0 = ks * 8;
        uint32_t a[2][4];
#pragma unroll
        for (int mt = 0; mt < 2; mt++) {
            const float* ap = Abase + mt * 16 * LDP + k0;
            a[mt][0] = f2u(ap[0]);
            a[mt][1] = f2u(ap[8 * LDP]);
            a[mt][2] = f2u(ap[4]);
            a[mt][3] = f2u(ap[8 * LDP + 4]);
        }
#pragma unroll
        for (int nt = 0; nt < 8; nt++) {
            const float* bp = Bbase + nt * 8 * LDP + k0;
            uint32_t b0 = f2u(bp[0]), b1 = f2u(bp[4]);
            mma8(C[0][nt], a[0], b0, b1);
            mma8(C[1][nt], a[1], b0, b1);
        }
    }
}

__device__ __forceinline__ void zeroC(float C[2][8][4]) {
#pragma unroll
    for (int i = 0; i < 2; i++)
#pragma unroll
        for (int j = 0; j < 8; j++)
#pragma unroll
            for (int l = 0; l < 4; l++) C[i][j][l] = 0.0f;
}

// Store C (+bias) into smem tile Cs (stride LDP). Optionally tf32-round.
template <bool DOCVT>
__device__ __forceinline__ void store_C_bias(float* Cs, const float C[2][8][4],
                                             const float* __restrict__ bias,
                                             int warp, int lane) {
    int mw = warp >> 1, nw = warp & 1;
    int qrow = lane >> 2, qk = lane & 3;
#pragma unroll
    for (int nt = 0; nt < 8; nt++) {
        int col = nw * 64 + nt * 8 + 2 * qk;
        float2 bb = *reinterpret_cast<const float2*>(bias + col);
#pragma unroll
        for (int mt = 0; mt < 2; mt++) {
            int r = mw * 32 + mt * 16 + qrow;
            float2 lo = make_float2(C[mt][nt][0] + bb.x, C[mt][nt][1] + bb.y);
            float2 hi = make_float2(C[mt][nt][2] + bb.x, C[mt][nt][3] + bb.y);
            if (DOCVT) {
                lo.x = cvt_tf32(lo.x); lo.y = cvt_tf32(lo.y);
                hi.x = cvt_tf32(hi.x); hi.y = cvt_tf32(hi.y);
            }
            *reinterpret_cast<float2*>(Cs + r * LDP + col) = lo;
            *reinterpret_cast<float2*>(Cs + (r + 8) * LDP + col) = hi;
        }
    }
}

// ---------------------------------------------------------------------------
// small helpers
// ---------------------------------------------------------------------------
__device__ __forceinline__ void load16(float* x, const float* p) {
#pragma unroll
    for (int q4 = 0; q4 < 4; q4++) {
        float4 v = *reinterpret_cast<const float4*>(p + q4 * 4);
        x[q4 * 4] = v.x; x[q4 * 4 + 1] = v.y; x[q4 * 4 + 2] = v.z; x[q4 * 4 + 3] = v.w;
    }
}
__device__ __forceinline__ void store16(float* p, const float* x) {
#pragma unroll
    for (int q4 = 0; q4 < 4; q4++)
        *reinterpret_cast<float4*>(p + q4 * 4) =
            make_float4(x[q4 * 4], x[q4 * 4 + 1], x[q4 * 4 + 2], x[q4 * 4 + 3]);
}
__device__ __forceinline__ void softmax16(float* x) {
    float mx = x[0];
#pragma unroll
    for (int e = 1; e < 16; e++) mx = fmaxf(mx, x[e]);
    float s = 0.0f;
#pragma unroll
    for (int e = 0; e < 16; e++) { x[e] = __expf(x[e] - mx); s += x[e]; }
    float inv = 1.0f / s;
#pragma unroll
    for (int e = 0; e < 16; e++) x[e] *= inv;
}
__device__ __forceinline__ void rope16(float* x, const float* cs, const float* sn) {
#pragma unroll
    for (int j = 0; j < 8; j++) {
        float a = x[2 * j], b = x[2 * j + 1];
        x[2 * j]     = a * cs[j] - b * sn[j];
        x[2 * j + 1] = a * sn[j] + b * cs[j];
    }
}
__device__ __forceinline__ void make_rope(int pos, float* cs, float* sn) {
    float fp = (float)pos;
#pragma unroll
    for (int j = 0; j < 8; j++) __sincosf(fp * c_freq[j], &sn[j], &cs[j]);
}

// ---------------------------------------------------------------------------
// Kernel 1: Q path
// ---------------------------------------------------------------------------
__global__ void __launch_bounds__(256, 1)
kq_kernel(const float* __restrict__ Q, const float* __restrict__ Wq,
          const float* __restrict__ bq) {
    extern __shared__ float sm[];
    float* As = sm;             // 17408
    float* Ws = sm + 17408;     // 17408
    int tid = threadIdx.x, warp = tid >> 5, lane = tid & 31;
    int row0 = blockIdx.x * 128;
    int pos = (row0 & 2047) >> 8;   // constant within tile
    float cs[8], sn[8];
    make_rope(pos, cs, sn);

    load_tile_cvt(As, Q + (size_t)row0 * 128, tid);
    load_tile_cvt(Ws, Wq, tid);
    __syncthreads();

    float C[2][8][4];
    zeroC(C);
    mma_gemm128(As, Ws, C, warp, lane);
    __syncthreads();
    store_C_bias<false>(As, C, bq, warp, lane);
    __syncthreads();

#pragma unroll
    for (int it = 0; it < 4; it++) {
        int task = it * 256 + tid;
        int r = task >> 3, g = task & 7;
        float x[16];
        load16(x, As + r * LDP + g * 16);
        softmax16(x);
        rope16(x, cs, sn);
        store16(g_q + (size_t)(row0 + r) * 128 + g * 16, x);
    }
}

// ---------------------------------------------------------------------------
// Kernel 2: edge K/V path, fused, mma for both GEMMs and kv reduction
// ---------------------------------------------------------------------------
__global__ void __launch_bounds__(256, 1)
kkv_kernel(const float* __restrict__ E,
           const float* __restrict__ Wk, const float* __restrict__ bk,
           const float* __restrict__ Wv, const float* __restrict__ bv) {
    extern __shared__ float sm[];
    float* As = sm;              // edge tile, later V tile (tf32)
    float* Ws = sm + 17408;      // Wk, then Wv, then reduction buffer
    float* Ks = sm + 34816;      // k tile
    int tid = threadIdx.x, warp = tid >> 5, lane = tid & 31;
    int blk = blockIdx.x;
    int row0 = blk * 128;
    int pos = (row0 & 8191) >> 10;  // constant within tile
    float cs[8], sn[8];
    make_rope(pos, cs, sn);

    load_tile_cvt(As, E + (size_t)row0 * 128, tid);
    load_tile_cvt(Ws, Wk, tid);
    __syncthreads();

    float C[2][8][4];
    zeroC(C);
    mma_gemm128(As, Ws, C, warp, lane);           // k = edge @ Wk^T
    store_C_bias<false>(Ks, C, bk, warp, lane);   // Ks untouched by gemm
    __syncthreads();

    // k epilogue: rope -> softmax -> tf32 round, in place
#pragma unroll
    for (int it = 0; it < 4; it++) {
        int task = it * 256 + tid;
        int r = task >> 3, g = task & 7;
        float x[16];
        load16(x, Ks + r * LDP + g * 16);
        rope16(x, cs, sn);
        softmax16(x);
#pragma unroll
        for (int e = 0; e < 16; e++) x[e] = cvt_tf32(x[e]);
        store16(Ks + r * LDP + g * 16, x);
    }
    load_tile_cvt(Ws, Wv, tid);   // safe: all Wk reads done at last sync
    __syncthreads();

    zeroC(C);
    mma_gemm128(As, Ws, C, warp, lane);           // v = edge @ Wv^T
    __syncthreads();                               // all As reads done
    store_C_bias<true>(As, C, bv, warp, lane);    // V (tf32) over edge tile
    __syncthreads();

    // kv = Kt(16x1024) @ V(1024x16) + ksum via mma; warp handles 16 ksteps
    int qrow = lane >> 2, qk = lane & 3;
    float Ckv[2][4] = {{0, 0, 0, 0}, {0, 0, 0, 0}};
    float s_lo = 0.0f, s_hi = 0.0f;
    for (int s = warp * 16; s < warp * 16 + 16; s++) {
        const float* kp = Ks + s * LDP + qk * 16 + qrow;
        uint32_t a[4];
        a[0] = f2u(kp[0]);        // d=qrow,  g=qk
        a[1] = f2u(kp[8]);        // d=qrow+8,g=qk
        a[2] = f2u(kp[64]);       // d=qrow,  g=qk+4
        a[3] = f2u(kp[72]);       // d=qrow+8,g=qk+4
        const float* vp = As + s * LDP + qk * 16 + qrow;
        uint32_t b0 = f2u(vp[0]),  b1 = f2u(vp[64]);   // e = qrow
        uint32_t c0 = f2u(vp[8]),  c1 = f2u(vp[72]);   // e = qrow+8
        mma8(Ckv[0], a, b0, b1);
        mma8(Ckv[1], a, c0, c1);
        s_lo += __uint_as_float(a[0]) + __uint_as_float(a[2]);
        s_hi += __uint_as_float(a[1]) + __uint_as_float(a[3]);
    }
    s_lo += __shfl_xor_sync(0xffffffffu, s_lo, 1);
    s_lo += __shfl_xor_sync(0xffffffffu, s_lo, 2);
    s_hi += __shfl_xor_sync(0xffffffffu, s_hi, 1);
    s_hi += __shfl_xor_sync(0xffffffffu, s_hi, 2);

    float* red = Ws;   // 8 x 272, Ws free now
#pragma unroll
    for (int nt = 0; nt < 2; nt++) {
        int e = nt * 8 + 2 * qk;
        red[warp * 272 + qrow * 17 + e]           = Ckv[nt][0];
        red[warp * 272 + qrow * 17 + e + 1]       = Ckv[nt][1];
        red[warp * 272 + (qrow + 8) * 17 + e]     = Ckv[nt][2];
        red[warp * 272 + (qrow + 8) * 17 + e + 1] = Ckv[nt][3];
    }
    if (qk == 0) {
        red[warp * 272 + qrow * 17 + 16]       = s_lo;
        red[warp * 272 + (qrow + 8) * 17 + 16] = s_hi;
    }
    __syncthreads();

    for (int e = tid; e < 272; e += 256) {
        float s = 0.0f;
#pragma unroll
        for (int w = 0; w < 8; w++) s += red[w * 272 + e];
        g_part[(size_t)blk * 272 + e] = s;
    }
}

// ---------------------------------------------------------------------------
// Kernel 3: deterministic reduction of per-tile partials
// ---------------------------------------------------------------------------
__global__ void kr_kernel() {
    int bt = blockIdx.x;
    int tid = threadIdx.x;  // 272
    float s = 0.0f;
    for (int i = 0; i < 64; i++)
        s += g_part[(size_t)(bt * 64 + i) * 272 + tid];
    int d1 = tid / 17, col = tid % 17;
    if (col < 16) g_kv[bt * 256 + d1 * 16 + col] = s;
    else          g_ksum[bt * 16 + d1] = s;
}

// ---------------------------------------------------------------------------
// Kernel 4: output: build Y, then Y @ Wo^T + bo
// ---------------------------------------------------------------------------
__global__ void __launch_bounds__(256, 1)
ko_kernel(const float* __restrict__ Wo, const float* __restrict__ bo,
          float* __restrict__ out) {
    extern __shared__ float sm[];
    float* Ys  = sm;             // 17408 (Y, then output stage)
    float* Ws  = sm + 17408;     // 17408
    float* kvs = sm + 34816;     // 2048
    float* kss = sm + 36864;     // 128
    int tid = threadIdx.x, warp = tid >> 5, lane = tid & 31;
    int r0 = blockIdx.x * 128;
    int b = r0 >> 14;

    for (int idx = tid; idx < 2048; idx += 256) kvs[idx] = g_kv[b * 2048 + idx];
    if (tid < 128) kss[tid] = g_ksum[b * 128 + tid];
    load_tile_cvt(Ws, Wo, tid);
    __syncthreads();

#pragma unroll
    for (int it = 0; it < 4; it++) {
        int task = it * 256 + tid;
        int r = task >> 3, t = task & 7;
        int spp = (r0 + r) & 16383;
        int n = spp >> 3, g = spp & 7;
        const float* qp = g_q + (size_t)((b * 8 + t) * 2048 + n) * 128 + g * 16;
        float q16[16];
        load16(q16, qp);
        float den = 0.0f;
#pragma unroll
        for (int d = 0; d < 16; d++) den = fmaf(q16[d], kss[t * 16 + d], den);
        float dinv = 1.0f / fmaxf(den, 1e-8f);
        float a16[16];
#pragma unroll
        for (int e = 0; e < 16; e++) a16[e] = 0.0f;
#pragma unroll
        for (int d = 0; d < 16; d++) {
            float qd = q16[d];
#pragma unroll
            for (int e = 0; e < 16; e++)
                a16[e] = fmaf(qd, kvs[t * 256 + d * 16 + e], a16[e]);
        }
        float o16[16];
#pragma unroll
        for (int e = 0; e < 16; e++) o16[e] = cvt_tf32(q16[e] + a16[e] * dinv);
        store16(Ys + r * LDP + t * 16, o16);
    }
    __syncthreads();

    float C[2][8][4];
    zeroC(C);
    mma_gemm128(Ys, Ws, C, warp, lane);
    __syncthreads();
    store_C_bias<false>(Ys, C, bo, warp, lane);  // stage into Ys region
    __syncthreads();

    // coalesced copy stage -> gmem
    float4* o4 = reinterpret_cast<float4*>(out + (size_t)r0 * 128);
#pragma unroll
    for (int k = 0; k < 16; k++) {
        int idx = tid + 256 * k;
        int row = idx >> 5, c4 = idx & 31;
        o4[idx] = *reinterpret_cast<const float4*>(Ys + row * LDP + c4 * 4);
    }
}

// ---------------------------------------------------------------------------
// Host launcher
// ---------------------------------------------------------------------------
extern "C" void kernel_launch(void* const* d_in, const int* in_sizes, int n_in,
                              void* d_out, int out_size) {
    const float* edge = (const float*)d_in[1];
    const float* qd   = (const float*)d_in[2];
    const float* Wq   = (const float*)d_in[3];
    const float* bq   = (const float*)d_in[4];
    const float* Wk1  = (const float*)d_in[9];
    const float* bk1  = (const float*)d_in[10];
    const float* Wv1  = (const float*)d_in[11];
    const float* bv1  = (const float*)d_in[12];
    const float* Wo   = (const float*)d_in[13];
    const float* bo   = (const float*)d_in[14];
    float* out = (float*)d_out;

    cudaFuncSetAttribute(kq_kernel,  cudaFuncAttributeMaxDynamicSharedMemorySize, 139264);
    cudaFuncSetAttribute(kkv_kernel, cudaFuncAttributeMaxDynamicSharedMemorySize, 208896);
    cudaFuncSetAttribute(ko_kernel,  cudaFuncAttributeMaxDynamicSharedMemorySize, 147968);

    kq_kernel<<<KQ_BLOCKS, 256, 139264>>>(qd, Wq, bq);
    kkv_kernel<<<KKV_BLOCKS, 256, 208896>>>(edge, Wk1, bk1, Wv1, bv1);
    kr_kernel<<<32, 272>>>();
    ko_kernel<<<KO_BLOCKS, 256, 147968>>>(Wo, bo, out);
}